// round 7
// baseline (speedup 1.0000x reference)
#include <cuda_runtime.h>
#include <cuda_bf16.h>
#include <cstdint>

// ---------------------------------------------------------------------------
// Problem constants
// ---------------------------------------------------------------------------
#define IMGS 24          // B*T
#define HWDIM 56
#define WSZ 7
#define NWIN (IMGS*64)          // 1536
#define NTOK 49
#define M_TOTAL (NWIN*NTOK)     // 75264
#define DMODEL 384
#define NHEAD 12
#define HD 32
#define QKV_N 1152
#define BK 16
#define STAGES 3
#define TILE_STG (128*20)       // one 128x16 tile, row stride 20 floats

// ---------------------------------------------------------------------------
// Scratch (device globals; allocation is forbidden)
// ---------------------------------------------------------------------------
__device__ float g_xw [M_TOTAL * DMODEL];     // LN'd, windowed, tf32-rounded
__device__ float g_qkv[M_TOTAL * QKV_N];      // qkv projection (fp32)
__device__ float g_att[M_TOTAL * DMODEL];     // attention out, tf32-rounded
__device__ float g_wqt[QKV_N * DMODEL];       // qkv_w transposed [N][K], tf32
__device__ float g_wpt[DMODEL * DMODEL];      // proj_w transposed [N][K], tf32

// ---------------------------------------------------------------------------
// Helpers
// ---------------------------------------------------------------------------
__device__ __forceinline__ float to_tf32(float x) {
    asm("cvt.rna.tf32.f32 %0, %0;" : "+f"(x));
    return x;
}

__device__ __forceinline__ void cp16(uint32_t dst, const void* src) {
    asm volatile("cp.async.cg.shared.global [%0], [%1], 16;\n" :: "r"(dst), "l"(src));
}

// exp(x) on the FMA pipe.  rel err ~2e-6.
__device__ __forceinline__ float fast_exp(float x) {
    const float LOG2E = 1.4426950408889634f;
    float y0 = x * LOG2E;
    float t  = __fadd_rn(y0, 12582912.0f);
    int   n  = __float_as_int(t) - 0x4B400000;
    float fn = __fadd_rn(t, -12582912.0f);
    float f  = y0 - fn;
    float p  = 1.3333558e-3f;
    p = fmaf(p, f, 9.6181293e-3f);
    p = fmaf(p, f, 5.5504109e-2f);
    p = fmaf(p, f, 2.4022651e-1f);
    p = fmaf(p, f, 6.9314718e-1f);
    p = fmaf(p, f, 1.0f);
    n = max(n, -126);
    float s = __int_as_float((n + 127) << 23);
    return s * p;
}

#define MMA_TF32(C, A, B)                                                     \
    asm volatile(                                                             \
        "mma.sync.aligned.m16n8k8.row.col.f32.tf32.tf32.f32 "                 \
        "{%0,%1,%2,%3}, {%4,%5,%6,%7}, {%8,%9}, {%0,%1,%2,%3};\n"             \
        : "+f"((C)[0]), "+f"((C)[1]), "+f"((C)[2]), "+f"((C)[3])              \
        : "r"((A)[0]), "r"((A)[1]), "r"((A)[2]), "r"((A)[3]),                 \
          "r"((B)[0]), "r"((B)[1]))

// ldmatrix x4 (b16 path; on 32-bit data each 8x8-b16 matrix = 8x4 tf32 tile,
// thread t holds element [t/4][t%4] -- exactly the tf32 mma fragment pattern)
#define LDSM4(R0, R1, R2, R3, addr)                                           \
    asm volatile("ldmatrix.sync.aligned.m8n8.x4.shared.b16 {%0,%1,%2,%3}, [%4];" \
        : "=r"(R0), "=r"(R1), "=r"(R2), "=r"(R3) : "r"(addr))

// ---------------------------------------------------------------------------
// Kernel 0: transpose [K][N] weights to [N][K], rounding to tf32
// ---------------------------------------------------------------------------
__global__ void cvt_transpose_kernel(const float* __restrict__ src, float* __restrict__ dst,
                                     int N, int K)
{
    int i = blockIdx.x * 256 + threadIdx.x;     // output index, k fastest
    if (i < N * K) {
        int n = i / K, k = i - n * K;
        dst[i] = to_tf32(src[(size_t)k * N + n]);
    }
}

// ---------------------------------------------------------------------------
// Kernel 1: LayerNorm + window partition (tf32-rounded output)
// ---------------------------------------------------------------------------
__global__ __launch_bounds__(96)
void ln_window_kernel(const float* __restrict__ x, const float* __restrict__ g,
                      const float* __restrict__ b, float* __restrict__ xw)
{
    int m = blockIdx.x;
    int win = m / NTOK, n = m - win * NTOK;
    int img = win >> 6;
    int wy  = (win >> 3) & 7;
    int wx  = win & 7;
    int iy = n / WSZ, ix = n - iy * WSZ;
    int h = wy * WSZ + iy;
    int w = wx * WSZ + ix;
    const float* xin = x + ((size_t)(img * HWDIM + h) * HWDIM + w) * DMODEL;

    int t = threadIdx.x;
    float4 v = ((const float4*)xin)[t];
    float s  = v.x + v.y + v.z + v.w;
    float ss = v.x*v.x + v.y*v.y + v.z*v.z + v.w*v.w;
    #pragma unroll
    for (int off = 16; off; off >>= 1) {
        s  += __shfl_xor_sync(0xffffffffu, s,  off);
        ss += __shfl_xor_sync(0xffffffffu, ss, off);
    }
    __shared__ float sm[3], sm2[3];
    int wid = t >> 5, lane = t & 31;
    if (!lane) { sm[wid] = s; sm2[wid] = ss; }
    __syncthreads();
    s  = sm[0] + sm[1] + sm[2];
    ss = sm2[0] + sm2[1] + sm2[2];
    float mu  = s * (1.f / DMODEL);
    float var = ss * (1.f / DMODEL) - mu * mu;
    float rstd = rsqrtf(var + 1e-5f);

    float4 gg = ((const float4*)g)[t];
    float4 bb = ((const float4*)b)[t];
    float4 r;
    r.x = to_tf32((v.x - mu) * rstd * gg.x + bb.x);
    r.y = to_tf32((v.y - mu) * rstd * gg.y + bb.y);
    r.z = to_tf32((v.z - mu) * rstd * gg.z + bb.z);
    r.w = to_tf32((v.w - mu) * rstd * gg.w + bb.w);
    ((float4*)(xw + (size_t)m * DMODEL))[t] = r;
}

// ---------------------------------------------------------------------------
// tf32 tensor-core GEMM with ldmatrix fragment loads.
// C[M,NC] = A[M,384] @ Wt[NC,384]^T + bias.  Wt is N-major ([n][k]).
// Both smem tiles stored [row][16 k-floats], row stride 20 (conflict-free for
// the 8-row LDSM address sets AND 16B-aligned rows).
// 3-stage cp.async, one barrier per K-iter.
// MODE 0: row-major store.  MODE 1: un-window scatter.
// ---------------------------------------------------------------------------
template<int NC, int MODE>
__global__ __launch_bounds__(256, 2)
void mma_gemm(const float* __restrict__ A, const float* __restrict__ Wt,
              const float* __restrict__ bias, float* __restrict__ C)
{
    extern __shared__ float smem[];
    float* As = smem;                      // STAGES * TILE_STG
    float* Bs = smem + STAGES * TILE_STG;  // STAGES * TILE_STG

    const int tid   = threadIdx.x;
    const int lane  = tid & 31;
    const int warp  = tid >> 5;
    const int mwarp = warp >> 1;           // 0..3
    const int nwarp = warp & 1;            // 0..1
    const int m0 = blockIdx.y * 128;
    const int n0 = blockIdx.x * 128;

    const uint32_t sA = (uint32_t)__cvta_generic_to_shared(As);
    const uint32_t sB = (uint32_t)__cvta_generic_to_shared(Bs);

    float c[2][8][4];
    #pragma unroll
    for (int i = 0; i < 2; i++)
        #pragma unroll
        for (int j = 0; j < 8; j++)
            #pragma unroll
            for (int q = 0; q < 4; q++) c[i][j][q] = 0.f;

    auto load_stage = [&](int kt, int buf) {
        int k0 = kt * BK;
        #pragma unroll
        for (int i = 0; i < 2; i++) {
            int idx = tid + i * 256;       // 0..511
            int row = idx >> 2, q = idx & 3;
            cp16(sA + (buf * TILE_STG + row * 20 + q * 4) * 4,
                 A  + (size_t)(m0 + row) * DMODEL + k0 + q * 4);
            cp16(sB + (buf * TILE_STG + row * 20 + q * 4) * 4,
                 Wt + (size_t)(n0 + row) * DMODEL + k0 + q * 4);
        }
        asm volatile("cp.async.commit_group;\n");
    };

    load_stage(0, 0);
    load_stage(1, 1);

    const int KT = DMODEL / BK;   // 24
    for (int kt = 0; kt < KT; kt++) {
        int buf = kt % STAGES;
        if (kt + 1 < KT) {
            asm volatile("cp.async.wait_group 1;\n" ::: "memory");
        } else {
            asm volatile("cp.async.wait_group 0;\n" ::: "memory");
        }
        __syncthreads();
        if (kt + 2 < KT)
            load_stage(kt + 2, (kt + 2) % STAGES);

        #pragma unroll
        for (int ks = 0; ks < 2; ks++) {
            int k = ks * 8;
            uint32_t a[2][4], rb[4][4];
            // A fragments: matrix mi -> row += (mi&1)*8, col += (mi>>1)*4
            #pragma unroll
            for (int mt = 0; mt < 2; mt++) {
                int row = mwarp * 32 + mt * 16 + ((lane >> 3) & 1) * 8 + (lane & 7);
                int col = k + ((lane >> 4) << 2);
                uint32_t addr = sA + (buf * TILE_STG + row * 20 + col) * 4;
                LDSM4(a[mt][0], a[mt][1], a[mt][2], a[mt][3], addr);
            }
            // B fragments: LDSM j covers n-tiles 2j,2j+1:
            //   matrix mi -> n += (mi>>1)*8, kk += (mi&1)*4
            //   rb[j] = { b0(nt=2j), b1(nt=2j), b0(nt=2j+1), b1(nt=2j+1) }
            #pragma unroll
            for (int j = 0; j < 4; j++) {
                int n  = nwarp * 64 + j * 16 + (lane >> 4) * 8 + (lane & 7);
                int kk = k + ((lane >> 3) & 1) * 4;
                uint32_t addr = sB + (buf * TILE_STG + n * 20 + kk) * 4;
                LDSM4(rb[j][0], rb[j][1], rb[j][2], rb[j][3], addr);
            }
            #pragma unroll
            for (int mt = 0; mt < 2; mt++)
                #pragma unroll
                for (int nt = 0; nt < 8; nt++) {
                    uint32_t bfr[2] = { rb[nt >> 1][(nt & 1) * 2],
                                        rb[nt >> 1][(nt & 1) * 2 + 1] };
                    MMA_TF32(c[mt][nt], a[mt], bfr);
                }
        }
    }

    #pragma unroll
    for (int mt = 0; mt < 2; mt++) {
        #pragma unroll
        for (int half = 0; half < 2; half++) {
            int m = m0 + mwarp * 32 + mt * 16 + (lane >> 2) + half * 8;
            float* op;
            if (MODE == 0) {
                op = C + (size_t)m * NC;
            } else {
                int win = m / NTOK, n = m - win * NTOK;
                int img = win >> 6;
                int wy = (win >> 3) & 7;
                int wx = win & 7;
                int iy = n / WSZ, ix = n - iy * WSZ;
                int ro = (img * HWDIM + wy * WSZ + iy) * HWDIM + wx * WSZ + ix;
                op = C + (size_t)ro * DMODEL;
            }
            #pragma unroll
            for (int nt = 0; nt < 8; nt++) {
                int col = n0 + nwarp * 64 + nt * 8 + 2 * (lane & 3);
                float2 v;
                v.x = c[mt][nt][half * 2 + 0] + __ldg(&bias[col]);
                v.y = c[mt][nt][half * 2 + 1] + __ldg(&bias[col + 1]);
                *(float2*)(op + col) = v;
            }
        }
    }
}

// ---------------------------------------------------------------------------
// Kernel 3: tensor-core windowed attention (unchanged from R4 best).
// ---------------------------------------------------------------------------
__global__ __launch_bounds__(128)
void attn_mma_kernel(const float* __restrict__ qkv, const float* __restrict__ bias_table,
                     float* __restrict__ attout)
{
    __shared__ float qs[64 * 36];
    __shared__ float ks[56 * 36];
    __shared__ float vs[56 * 40];
    __shared__ float Ps[64 * 60];
    __shared__ float sb[169];

    const int blk  = blockIdx.x;
    const int win  = blk / NHEAD;
    const int head = blk - win * NHEAD;
    const int tid  = threadIdx.x;
    const int lane = tid & 31;
    const int warp = tid >> 5;
    const float scale = 0.17677669529663687f;

    const size_t base = (size_t)win * NTOK * QKV_N + head * HD;

    for (int idx = tid; idx < NTOK * 8; idx += 128) {
        int n = idx >> 3, cq = idx & 7;
        const float* p = qkv + base + (size_t)n * QKV_N + cq * 4;
        float4 qv = *(const float4*)(p);
        qv.x = to_tf32(qv.x * scale); qv.y = to_tf32(qv.y * scale);
        qv.z = to_tf32(qv.z * scale); qv.w = to_tf32(qv.w * scale);
        *(float4*)&qs[n * 36 + cq * 4] = qv;
        float4 kv = *(const float4*)(p + DMODEL);
        kv.x = to_tf32(kv.x); kv.y = to_tf32(kv.y);
        kv.z = to_tf32(kv.z); kv.w = to_tf32(kv.w);
        *(float4*)&ks[n * 36 + cq * 4] = kv;
        float4 vv = *(const float4*)(p + 2 * DMODEL);
        vv.x = to_tf32(vv.x); vv.y = to_tf32(vv.y);
        vv.z = to_tf32(vv.z); vv.w = to_tf32(vv.w);
        *(float4*)&vs[n * 40 + cq * 4] = vv;
    }
    if (tid < 56) {
        int n = 49 + (tid >> 3), cq = tid & 7;
        *(float4*)&ks[n * 36 + cq * 4] = make_float4(0.f, 0.f, 0.f, 0.f);
        *(float4*)&vs[n * 40 + cq * 4] = make_float4(0.f, 0.f, 0.f, 0.f);
    }
    for (int idx = tid; idx < 169; idx += 128)
        sb[idx] = bias_table[idx * NHEAD + head];
    __syncthreads();

    float cS[7][4];
    #pragma unroll
    for (int nt = 0; nt < 7; nt++)
        #pragma unroll
        for (int q = 0; q < 4; q++) cS[nt][q] = 0.f;

    const int r0 = warp * 16 + (lane >> 2);
    #pragma unroll
    for (int kt = 0; kt < 4; kt++) {
        int kk = kt * 8 + (lane & 3);
        uint32_t a[4];
        a[0] = __float_as_uint(qs[r0 * 36 + kk]);
        a[1] = __float_as_uint(qs[(r0 + 8) * 36 + kk]);
        a[2] = __float_as_uint(qs[r0 * 36 + kk + 4]);
        a[3] = __float_as_uint(qs[(r0 + 8) * 36 + kk + 4]);
        #pragma unroll
        for (int nt = 0; nt < 7; nt++) {
            int n = nt * 8 + (lane >> 2);
            uint32_t b[2];
            b[0] = __float_as_uint(ks[n * 36 + kk]);
            b[1] = __float_as_uint(ks[n * 36 + kk + 4]);
            MMA_TF32(cS[nt], a, b);
        }
    }

    #pragma unroll
    for (int h = 0; h < 2; h++) {
        int r = r0 + 8 * h;
        bool rvalid = (r < NTOK);
        int iy = r / WSZ, ix = r - iy * WSZ;
        float vals[14];
        float mx = -1e30f;
        #pragma unroll
        for (int nt = 0; nt < 7; nt++) {
            #pragma unroll
            for (int q = 0; q < 2; q++) {
                int col = nt * 8 + 2 * (lane & 3) + q;
                float vv = -1e30f;
                if (rvalid && col < NTOK) {
                    int jy = col / WSZ, jx = col - jy * WSZ;
                    vv = cS[nt][2 * h + q] + sb[(iy - jy + 6) * 13 + (ix - jx + 6)];
                }
                vals[nt * 2 + q] = vv;
                mx = fmaxf(mx, vv);
            }
        }
        mx = fmaxf(mx, __shfl_xor_sync(0xffffffffu, mx, 1));
        mx = fmaxf(mx, __shfl_xor_sync(0xffffffffu, mx, 2));
        float sum = 0.f;
        #pragma unroll
        for (int i = 0; i < 14; i++) {
            float e = fast_exp(vals[i] - mx);
            vals[i] = e;
            sum += e;
        }
        sum += __shfl_xor_sync(0xffffffffu, sum, 1);
        sum += __shfl_xor_sync(0xffffffffu, sum, 2);
        float inv = 1.f / sum;
        #pragma unroll
        for (int nt = 0; nt < 7; nt++)
            #pragma unroll
            for (int q = 0; q < 2; q++) {
                int col = nt * 8 + 2 * (lane & 3) + q;
                Ps[r * 60 + col] = to_tf32(vals[nt * 2 + q] * inv);
            }
    }
    __syncwarp();

    float o[4][4];
    #pragma unroll
    for (int nt = 0; nt < 4; nt++)
        #pragma unroll
        for (int q = 0; q < 4; q++) o[nt][q] = 0.f;

    #pragma unroll
    for (int kt = 0; kt < 7; kt++) {
        int kk = kt * 8 + (lane & 3);
        uint32_t a[4];
        a[0] = __float_as_uint(Ps[r0 * 60 + kk]);
        a[1] = __float_as_uint(Ps[(r0 + 8) * 60 + kk]);
        a[2] = __float_as_uint(Ps[r0 * 60 + kk + 4]);
        a[3] = __float_as_uint(Ps[(r0 + 8) * 60 + kk + 4]);
        #pragma unroll
        for (int nt = 0; nt < 4; nt++) {
            int d = nt * 8 + (lane >> 2);
            uint32_t b[2];
            b[0] = __float_as_uint(vs[kk * 40 + d]);
            b[1] = __float_as_uint(vs[(kk + 4) * 40 + d]);
            MMA_TF32(o[nt], a, b);
        }
    }

    #pragma unroll
    for (int h = 0; h < 2; h++) {
        int r = r0 + 8 * h;
        if (r < NTOK) {
            float* op = attout + (size_t)(win * NTOK + r) * DMODEL + head * HD;
            #pragma unroll
            for (int nt = 0; nt < 4; nt++) {
                int col = nt * 8 + 2 * (lane & 3);
                float2 v;
                v.x = to_tf32(o[nt][2 * h + 0]);
                v.y = to_tf32(o[nt][2 * h + 1]);
                *(float2*)(op + col) = v;
            }
        }
    }
}

// ---------------------------------------------------------------------------
// Launch
// ---------------------------------------------------------------------------
extern "C" void kernel_launch(void* const* d_in, const int* in_sizes, int n_in,
                              void* d_out, int out_size)
{
    const float* x      = (const float*)d_in[0];
    const float* ln_g   = (const float*)d_in[1];
    const float* ln_b   = (const float*)d_in[2];
    const float* qkv_w  = (const float*)d_in[3];
    const float* qkv_b  = (const float*)d_in[4];
    const float* proj_w = (const float*)d_in[5];
    const float* proj_b = (const float*)d_in[6];
    const float* relb   = (const float*)d_in[7];
    float* out = (float*)d_out;

    float *xw, *qkv, *att, *wqt, *wpt;
    cudaGetSymbolAddress((void**)&xw,  g_xw);
    cudaGetSymbolAddress((void**)&qkv, g_qkv);
    cudaGetSymbolAddress((void**)&att, g_att);
    cudaGetSymbolAddress((void**)&wqt, g_wqt);
    cudaGetSymbolAddress((void**)&wpt, g_wpt);

    const int gemm_smem = STAGES * TILE_STG * 2 * 4;   // 61440 B
    static int attr_set = 0;
    if (!attr_set) {
        cudaFuncSetAttribute(mma_gemm<QKV_N, 0>,
                             cudaFuncAttributeMaxDynamicSharedMemorySize, gemm_smem);
        cudaFuncSetAttribute(mma_gemm<DMODEL, 1>,
                             cudaFuncAttributeMaxDynamicSharedMemorySize, gemm_smem);
        attr_set = 1;
    }

    cvt_transpose_kernel<<<(QKV_N * DMODEL + 255) / 256, 256>>>(qkv_w, wqt, QKV_N, DMODEL);
    cvt_transpose_kernel<<<(DMODEL * DMODEL + 255) / 256, 256>>>(proj_w, wpt, DMODEL, DMODEL);
    ln_window_kernel<<<M_TOTAL, 96>>>(x, ln_g, ln_b, xw);
    mma_gemm<QKV_N, 0><<<dim3(QKV_N / 128, M_TOTAL / 128), 256, gemm_smem>>>(xw, wqt, qkv_b, qkv);
    attn_mma_kernel<<<NWIN * NHEAD, 128>>>(qkv, relb, att);
    mma_gemm<DMODEL, 1><<<dim3(DMODEL / 128, M_TOTAL / 128), 256, gemm_smem>>>(att, wpt, proj_b, out);
}

// round 8
// speedup vs baseline: 1.7318x; 1.7318x over previous
#include <cuda_runtime.h>
#include <cuda_fp16.h>
#include <cstdint>

// ---------------------------------------------------------------------------
// Problem constants
// ---------------------------------------------------------------------------
#define IMGS 24          // B*T
#define HWDIM 56
#define WSZ 7
#define NWIN (IMGS*64)          // 1536
#define NTOK 49
#define M_TOTAL (NWIN*NTOK)     // 75264
#define DMODEL 384
#define NHEAD 12
#define HD 32
#define QKV_N 1152
#define BKH 32                  // halves per k-chunk
#define STAGES 3
#define TILE_H (128*40)         // one 128x32h tile, row stride 40 halves
#define TILE_B (TILE_H*2)       // bytes

// ---------------------------------------------------------------------------
// Scratch (device globals; allocation is forbidden)
// ---------------------------------------------------------------------------
__device__ __half g_xw [M_TOTAL * DMODEL];     // LN'd, windowed, fp16
__device__ __half g_qkv[M_TOTAL * QKV_N];      // qkv projection, fp16
__device__ __half g_att[M_TOTAL * DMODEL];     // attention out, fp16
__device__ __half g_wqt[QKV_N * DMODEL];       // qkv_w transposed [N][K], fp16
__device__ __half g_wpt[DMODEL * DMODEL];      // proj_w transposed [N][K], fp16

// ---------------------------------------------------------------------------
// Helpers
// ---------------------------------------------------------------------------
__device__ __forceinline__ void cp16(uint32_t dst, const void* src) {
    asm volatile("cp.async.cg.shared.global [%0], [%1], 16;\n" :: "r"(dst), "l"(src));
}

// exp(x) on the FMA pipe.  rel err ~2e-6.
__device__ __forceinline__ float fast_exp(float x) {
    const float LOG2E = 1.4426950408889634f;
    float y0 = x * LOG2E;
    float t  = __fadd_rn(y0, 12582912.0f);
    int   n  = __float_as_int(t) - 0x4B400000;
    float fn = __fadd_rn(t, -12582912.0f);
    float f  = y0 - fn;
    float p  = 1.3333558e-3f;
    p = fmaf(p, f, 9.6181293e-3f);
    p = fmaf(p, f, 5.5504109e-2f);
    p = fmaf(p, f, 2.4022651e-1f);
    p = fmaf(p, f, 6.9314718e-1f);
    p = fmaf(p, f, 1.0f);
    n = max(n, -126);
    float s = __int_as_float((n + 127) << 23);
    return s * p;
}

#define MMA_F16(C, A, B)                                                      \
    asm volatile(                                                             \
        "mma.sync.aligned.m16n8k16.row.col.f32.f16.f16.f32 "                  \
        "{%0,%1,%2,%3}, {%4,%5,%6,%7}, {%8,%9}, {%0,%1,%2,%3};\n"             \
        : "+f"((C)[0]), "+f"((C)[1]), "+f"((C)[2]), "+f"((C)[3])              \
        : "r"((A)[0]), "r"((A)[1]), "r"((A)[2]), "r"((A)[3]),                 \
          "r"((B)[0]), "r"((B)[1]))

#define LDSM4(R0, R1, R2, R3, addr)                                           \
    asm volatile("ldmatrix.sync.aligned.m8n8.x4.shared.b16 {%0,%1,%2,%3}, [%4];" \
        : "=r"(R0), "=r"(R1), "=r"(R2), "=r"(R3) : "r"(addr))

__device__ __forceinline__ uint32_t ldh2(const __half* p) {
    return *(const uint32_t*)p;
}

// ---------------------------------------------------------------------------
// Kernel 0: transpose [K][N] f32 weights to [N][K] fp16
// ---------------------------------------------------------------------------
__global__ void cvt_transpose_kernel(const float* __restrict__ src, __half* __restrict__ dst,
                                     int N, int K)
{
    int i = blockIdx.x * 256 + threadIdx.x;     // output index, k fastest
    if (i < N * K) {
        int n = i / K, k = i - n * K;
        dst[i] = __float2half_rn(src[(size_t)k * N + n]);
    }
}

// ---------------------------------------------------------------------------
// Kernel 1: LayerNorm + window partition (fp16 output)
// ---------------------------------------------------------------------------
__global__ __launch_bounds__(96)
void ln_window_kernel(const float* __restrict__ x, const float* __restrict__ g,
                      const float* __restrict__ b, __half* __restrict__ xw)
{
    int m = blockIdx.x;
    int win = m / NTOK, n = m - win * NTOK;
    int img = win >> 6;
    int wy  = (win >> 3) & 7;
    int wx  = win & 7;
    int iy = n / WSZ, ix = n - iy * WSZ;
    int h = wy * WSZ + iy;
    int w = wx * WSZ + ix;
    const float* xin = x + ((size_t)(img * HWDIM + h) * HWDIM + w) * DMODEL;

    int t = threadIdx.x;
    float4 v = ((const float4*)xin)[t];
    float s  = v.x + v.y + v.z + v.w;
    float ss = v.x*v.x + v.y*v.y + v.z*v.z + v.w*v.w;
    #pragma unroll
    for (int off = 16; off; off >>= 1) {
        s  += __shfl_xor_sync(0xffffffffu, s,  off);
        ss += __shfl_xor_sync(0xffffffffu, ss, off);
    }
    __shared__ float sm[3], sm2[3];
    int wid = t >> 5, lane = t & 31;
    if (!lane) { sm[wid] = s; sm2[wid] = ss; }
    __syncthreads();
    s  = sm[0] + sm[1] + sm[2];
    ss = sm2[0] + sm2[1] + sm2[2];
    float mu  = s * (1.f / DMODEL);
    float var = ss * (1.f / DMODEL) - mu * mu;
    float rstd = rsqrtf(var + 1e-5f);

    float4 gg = ((const float4*)g)[t];
    float4 bb = ((const float4*)b)[t];
    __half2 h0 = __floats2half2_rn((v.x - mu) * rstd * gg.x + bb.x,
                                   (v.y - mu) * rstd * gg.y + bb.y);
    __half2 h1 = __floats2half2_rn((v.z - mu) * rstd * gg.z + bb.z,
                                   (v.w - mu) * rstd * gg.w + bb.w);
    uint2 o;
    o.x = *(uint32_t*)&h0;
    o.y = *(uint32_t*)&h1;
    ((uint2*)(xw + (size_t)m * DMODEL))[t] = o;
}

// ---------------------------------------------------------------------------
// fp16 tensor-core GEMM: C[M,NC] = A[M,384] @ Wt[NC,384]^T + bias.
// Wt is N-major ([n][k]).  smem tiles [row][32 halves], stride 40 halves
// (conflict-free 8-row LDSM sets; 16B-aligned rows).  m16n8k16, f32 accum.
// 3-stage cp.async, one barrier per K-iter.
// MODE 0: fp16 row-major store.  MODE 1: f32 un-window scatter.
// ---------------------------------------------------------------------------
template<int NC, int MODE>
__global__ __launch_bounds__(256, 2)
void mma_gemm(const __half* __restrict__ A, const __half* __restrict__ Wt,
              const float* __restrict__ bias, void* __restrict__ Cout)
{
    extern __shared__ __half smem[];
    const uint32_t sA = (uint32_t)__cvta_generic_to_shared(smem);
    const uint32_t sB = sA + STAGES * TILE_B;

    const int tid   = threadIdx.x;
    const int lane  = tid & 31;
    const int warp  = tid >> 5;
    const int mwarp = warp >> 1;           // 0..3
    const int nwarp = warp & 1;            // 0..1
    const int m0 = blockIdx.y * 128;
    const int n0 = blockIdx.x * 128;

    float c[2][8][4];
    #pragma unroll
    for (int i = 0; i < 2; i++)
        #pragma unroll
        for (int j = 0; j < 8; j++)
            #pragma unroll
            for (int q = 0; q < 4; q++) c[i][j][q] = 0.f;

    auto load_stage = [&](int kt, int buf) {
        int k0 = kt * BKH;
        #pragma unroll
        for (int i = 0; i < 2; i++) {
            int idx = tid + i * 256;       // 0..511: 128 rows x 4 16B-quads
            int row = idx >> 2, q = idx & 3;
            cp16(sA + buf * TILE_B + (row * 40 + q * 8) * 2,
                 A  + (size_t)(m0 + row) * DMODEL + k0 + q * 8);
            cp16(sB + buf * TILE_B + (row * 40 + q * 8) * 2,
                 Wt + (size_t)(n0 + row) * DMODEL + k0 + q * 8);
        }
        asm volatile("cp.async.commit_group;\n");
    };

    load_stage(0, 0);
    load_stage(1, 1);

    const int KT = DMODEL / BKH;   // 12
    for (int kt = 0; kt < KT; kt++) {
        int buf = kt % STAGES;
        if (kt + 1 < KT) {
            asm volatile("cp.async.wait_group 1;\n" ::: "memory");
        } else {
            asm volatile("cp.async.wait_group 0;\n" ::: "memory");
        }
        __syncthreads();
        if (kt + 2 < KT)
            load_stage(kt + 2, (kt + 2) % STAGES);

        #pragma unroll
        for (int ks = 0; ks < 2; ks++) {            // two k16 steps
            uint32_t a[2][4], rb[4][4];
            // A: matrices {rows0-7,k0}{rows8-15,k0}{rows0-7,k8}{rows8-15,k8}
            #pragma unroll
            for (int mt = 0; mt < 2; mt++) {
                int row = mwarp * 32 + mt * 16 + ((lane >> 3) & 1) * 8 + (lane & 7);
                uint32_t addr = sA + buf * TILE_B + row * 80 + ks * 32 + (lane >> 4) * 16;
                LDSM4(a[mt][0], a[mt][1], a[mt][2], a[mt][3], addr);
            }
            // B: LDSM j covers n-tiles 2j (m0,m1 = k0,k8) and 2j+1 (m2,m3)
            #pragma unroll
            for (int j = 0; j < 4; j++) {
                int nrow = nwarp * 64 + j * 16 + (lane >> 4) * 8 + (lane & 7);
                uint32_t addr = sB + buf * TILE_B + nrow * 80 + ks * 32 + ((lane >> 3) & 1) * 16;
                LDSM4(rb[j][0], rb[j][1], rb[j][2], rb[j][3], addr);
            }
            #pragma unroll
            for (int mt = 0; mt < 2; mt++)
                #pragma unroll
                for (int nt = 0; nt < 8; nt++) {
                    uint32_t bfr[2] = { rb[nt >> 1][(nt & 1) * 2],
                                        rb[nt >> 1][(nt & 1) * 2 + 1] };
                    MMA_F16(c[mt][nt], a[mt], bfr);
                }
        }
    }

    #pragma unroll
    for (int mt = 0; mt < 2; mt++) {
        #pragma unroll
        for (int half = 0; half < 2; half++) {
            int m = m0 + mwarp * 32 + mt * 16 + (lane >> 2) + half * 8;
            #pragma unroll
            for (int nt = 0; nt < 8; nt++) {
                int col = n0 + nwarp * 64 + nt * 8 + 2 * (lane & 3);
                float vx = c[mt][nt][half * 2 + 0] + __ldg(&bias[col]);
                float vy = c[mt][nt][half * 2 + 1] + __ldg(&bias[col + 1]);
                if (MODE == 0) {
                    __half* op = (__half*)Cout + (size_t)m * NC;
                    __half2 hv = __floats2half2_rn(vx, vy);
                    *(__half2*)(op + col) = hv;
                } else {
                    int win = m / NTOK, n = m - win * NTOK;
                    int img = win >> 6;
                    int wy = (win >> 3) & 7;
                    int wx = win & 7;
                    int iy = n / WSZ, ix = n - iy * WSZ;
                    int ro = (img * HWDIM + wy * WSZ + iy) * HWDIM + wx * WSZ + ix;
                    float* op = (float*)Cout + (size_t)ro * DMODEL;
                    float2 v; v.x = vx; v.y = vy;
                    *(float2*)(op + col) = v;
                }
            }
        }
    }
}

// ---------------------------------------------------------------------------
// Kernel 3: fp16 tensor-core windowed attention.
// One block (128 threads, 4 warps) per (window, head).
// S = Q@K^T via m16n8k16 (K=32, 2 steps), scale+bias+softmax in f32 frags,
// P (fp16) @ V (fp16, stored transposed [d][j]) with K=64 (pads zeroed).
// ---------------------------------------------------------------------------
__global__ __launch_bounds__(128)
void attn_mma_kernel(const __half* __restrict__ qkv, const float* __restrict__ bias_table,
                     __half* __restrict__ attout)
{
    __shared__ __half qs[64 * 40];   // rows 49..63 garbage (row-confined)
    __shared__ __half ks[56 * 40];   // rows 49..55 garbage (masked cols)
    __shared__ __half vt[32 * 72];   // V transposed [d][j]; fully zeroed first
    __shared__ __half Ps[64 * 72];   // P; cols 56..63 zeroed
    __shared__ float  sb[169];

    const int blk  = blockIdx.x;
    const int win  = blk / NHEAD;
    const int head = blk - win * NHEAD;
    const int tid  = threadIdx.x;
    const int lane = tid & 31;
    const int warp = tid >> 5;
    const float scale = 0.17677669529663687f;

    // zero vt (288 uint4) and Ps cols 56..63 (64 rows x 16B)
    for (int idx = tid; idx < 288 + 64; idx += 128) {
        if (idx < 288)
            ((uint4*)vt)[idx] = make_uint4(0, 0, 0, 0);
        else
            *(uint4*)&Ps[(idx - 288) * 72 + 56] = make_uint4(0, 0, 0, 0);
    }
    __syncthreads();

    const size_t base = (size_t)win * NTOK * QKV_N + head * HD;

    // load q, k (16B = 8 halves per item), v transposed
    for (int idx = tid; idx < NTOK * 4; idx += 128) {
        int n = idx >> 2, cq = idx & 3;
        const __half* p = qkv + base + (size_t)n * QKV_N + cq * 8;
        *(uint4*)&qs[n * 40 + cq * 8] = *(const uint4*)(p);
        *(uint4*)&ks[n * 40 + cq * 8] = *(const uint4*)(p + DMODEL);
        uint4 vv = *(const uint4*)(p + 2 * DMODEL);
        const __half* vh = (const __half*)&vv;
        #pragma unroll
        for (int e = 0; e < 8; e++)
            vt[(cq * 8 + e) * 72 + n] = vh[e];
    }
    for (int idx = tid; idx < 169; idx += 128)
        sb[idx] = bias_table[idx * NHEAD + head];
    __syncthreads();

    // ---- S = q @ k^T : each warp 16 rows x 56 cols, K=32 (2 k16 steps) ----
    float cS[7][4];
    #pragma unroll
    for (int nt = 0; nt < 7; nt++)
        #pragma unroll
        for (int q = 0; q < 4; q++) cS[nt][q] = 0.f;

    const int r0 = warp * 16 + (lane >> 2);
    const int kc = 2 * (lane & 3);
    #pragma unroll
    for (int kt = 0; kt < 2; kt++) {
        int kk = kt * 16 + kc;
        uint32_t a[4];
        a[0] = ldh2(&qs[r0 * 40 + kk]);
        a[1] = ldh2(&qs[(r0 + 8) * 40 + kk]);
        a[2] = ldh2(&qs[r0 * 40 + kk + 8]);
        a[3] = ldh2(&qs[(r0 + 8) * 40 + kk + 8]);
        #pragma unroll
        for (int nt = 0; nt < 7; nt++) {
            int n = nt * 8 + (lane >> 2);
            uint32_t b[2];
            b[0] = ldh2(&ks[n * 40 + kk]);
            b[1] = ldh2(&ks[n * 40 + kk + 8]);
            MMA_F16(cS[nt], a, b);
        }
    }

    // ---- scale + bias + softmax per row (f32) ----
    #pragma unroll
    for (int h = 0; h < 2; h++) {
        int r = r0 + 8 * h;
        bool rvalid = (r < NTOK);
        int iy = r / WSZ, ix = r - iy * WSZ;
        float vals[14];
        float mx = -1e30f;
        #pragma unroll
        for (int nt = 0; nt < 7; nt++) {
            #pragma unroll
            for (int q = 0; q < 2; q++) {
                int col = nt * 8 + kc + q;
                float vv = -1e30f;
                if (rvalid && col < NTOK) {
                    int jy = col / WSZ, jx = col - jy * WSZ;
                    vv = fmaf(cS[nt][2 * h + q], scale, sb[(iy - jy + 6) * 13 + (ix - jx + 6)]);
                }
                vals[nt * 2 + q] = vv;
                mx = fmaxf(mx, vv);
            }
        }
        mx = fmaxf(mx, __shfl_xor_sync(0xffffffffu, mx, 1));
        mx = fmaxf(mx, __shfl_xor_sync(0xffffffffu, mx, 2));
        float sum = 0.f;
        #pragma unroll
        for (int i = 0; i < 14; i++) {
            float e = fast_exp(vals[i] - mx);
            vals[i] = e;
            sum += e;
        }
        sum += __shfl_xor_sync(0xffffffffu, sum, 1);
        sum += __shfl_xor_sync(0xffffffffu, sum, 2);
        float inv = 1.f / sum;
        #pragma unroll
        for (int nt = 0; nt < 7; nt++) {
            __half2 hv = __floats2half2_rn(vals[nt * 2] * inv, vals[nt * 2 + 1] * inv);
            *(__half2*)&Ps[r * 72 + nt * 8 + kc] = hv;
        }
    }
    __syncwarp();   // Ps rows are warp-private

    // ---- out = P @ V^T : each warp 16 rows x 32 dims, K=64 (4 k16 steps) ----
    float o[4][4];
    #pragma unroll
    for (int nt = 0; nt < 4; nt++)
        #pragma unroll
        for (int q = 0; q < 4; q++) o[nt][q] = 0.f;

    #pragma unroll
    for (int kt = 0; kt < 4; kt++) {
        int kk = kt * 16 + kc;
        uint32_t a[4];
        a[0] = ldh2(&Ps[r0 * 72 + kk]);
        a[1] = ldh2(&Ps[(r0 + 8) * 72 + kk]);
        a[2] = ldh2(&Ps[r0 * 72 + kk + 8]);
        a[3] = ldh2(&Ps[(r0 + 8) * 72 + kk + 8]);
        #pragma unroll
        for (int nt = 0; nt < 4; nt++) {
            int d = nt * 8 + (lane >> 2);
            uint32_t b[2];
            b[0] = ldh2(&vt[d * 72 + kk]);
            b[1] = ldh2(&vt[d * 72 + kk + 8]);
            MMA_F16(o[nt], a, b);
        }
    }

    #pragma unroll
    for (int h = 0; h < 2; h++) {
        int r = r0 + 8 * h;
        if (r < NTOK) {
            __half* op = attout + (size_t)(win * NTOK + r) * DMODEL + head * HD;
            #pragma unroll
            for (int nt = 0; nt < 4; nt++) {
                int col = nt * 8 + kc;
                __half2 hv = __floats2half2_rn(o[nt][2 * h + 0], o[nt][2 * h + 1]);
                *(__half2*)(op + col) = hv;
            }
        }
    }
}

// ---------------------------------------------------------------------------
// Launch
// ---------------------------------------------------------------------------
extern "C" void kernel_launch(void* const* d_in, const int* in_sizes, int n_in,
                              void* d_out, int out_size)
{
    const float* x      = (const float*)d_in[0];
    const float* ln_g   = (const float*)d_in[1];
    const float* ln_b   = (const float*)d_in[2];
    const float* qkv_w  = (const float*)d_in[3];
    const float* qkv_b  = (const float*)d_in[4];
    const float* proj_w = (const float*)d_in[5];
    const float* proj_b = (const float*)d_in[6];
    const float* relb   = (const float*)d_in[7];
    float* out = (float*)d_out;

    __half *xw, *qkv, *att, *wqt, *wpt;
    cudaGetSymbolAddress((void**)&xw,  g_xw);
    cudaGetSymbolAddress((void**)&qkv, g_qkv);
    cudaGetSymbolAddress((void**)&att, g_att);
    cudaGetSymbolAddress((void**)&wqt, g_wqt);
    cudaGetSymbolAddress((void**)&wpt, g_wpt);

    const int gemm_smem = STAGES * TILE_B * 2;   // 61440 B
    static int attr_set = 0;
    if (!attr_set) {
        cudaFuncSetAttribute(mma_gemm<QKV_N, 0>,
                             cudaFuncAttributeMaxDynamicSharedMemorySize, gemm_smem);
        cudaFuncSetAttribute(mma_gemm<DMODEL, 1>,
                             cudaFuncAttributeMaxDynamicSharedMemorySize, gemm_smem);
        attr_set = 1;
    }

    cvt_transpose_kernel<<<(QKV_N * DMODEL + 255) / 256, 256>>>(qkv_w, wqt, QKV_N, DMODEL);
    cvt_transpose_kernel<<<(DMODEL * DMODEL + 255) / 256, 256>>>(proj_w, wpt, DMODEL, DMODEL);
    ln_window_kernel<<<M_TOTAL, 96>>>(x, ln_g, ln_b, xw);
    mma_gemm<QKV_N, 0><<<dim3(QKV_N / 128, M_TOTAL / 128), 256, gemm_smem>>>(xw, wqt, qkv_b, qkv);
    attn_mma_kernel<<<NWIN * NHEAD, 128>>>(qkv, relb, att);
    mma_gemm<DMODEL, 1><<<dim3(DMODEL / 128, M_TOTAL / 128), 256, gemm_smem>>>(att, wpt, proj_b, out);
}